// round 1
// baseline (speedup 1.0000x reference)
#include <cuda_runtime.h>
#include <cuda_bf16.h>
#include <math_constants.h>

// Problem constants
#define Bc   32
#define Sc   511
#define Tc   512
#define Dc   512
#define Hc   8
#define HDc  64
#define Lc   4
#define PDc  32
#define FDc  448     // D - 2*PD
#define DFFc 2048
#define Mc   (Bc*Tc) // 16384 tokens

// ---------------- scratch (device globals; no allocation allowed) ----------
__device__ float g_x  [Mc*Dc];
__device__ float g_q  [Mc*Dc];
__device__ float g_k  [Mc*Dc];
__device__ float g_v  [Mc*Dc];
__device__ float g_att[Mc*Dc];
__device__ float g_tmp[Mc*Dc];
__device__ float g_ff [Mc*DFFc];

// ---------------- embedding + positional encoding ---------------------------
__global__ void embed_kernel(const float* __restrict__ runs,
                             const float* __restrict__ wickets,
                             const float* __restrict__ overs,
                             const int*   __restrict__ batters,
                             const int*   __restrict__ bowlers,
                             const float* __restrict__ pemb,
                             const float* __restrict__ Wf,
                             const float* __restrict__ bf,
                             const float* __restrict__ qtok,
                             float* __restrict__ x)
{
    int bt = blockIdx.x;
    int b  = bt / Tc;
    int t  = bt % Tc;
    int j  = threadIdx.x; // 0..511

    float val;
    if (t < Sc) {
        if (j < FDc) {
            float r = runs   [b*Sc + t];
            float w = wickets[b*Sc + t];
            float o = overs  [b*Sc + t];
            val = r*Wf[j] + w*Wf[FDc + j] + o*Wf[2*FDc + j] + bf[j];
        } else if (j < FDc + PDc) {
            val = pemb[batters[b*Sc + t]*PDc + (j - FDc)];
        } else {
            val = pemb[bowlers[b*Sc + t]*PDc + (j - FDc - PDc)];
        }
    } else {
        val = qtok[j];
    }
    // sinusoidal PE: channel 2i -> sin(t*div_i), 2i+1 -> cos, div_i = exp(-2i*ln(1e4)/512)
    int   i2  = j & ~1;
    float dv  = expf((float)i2 * -0.0179889460390111f); // ln(10000)/512
    float ang = (float)t * dv;
    val += (j & 1) ? cosf(ang) : sinf(ang);
    x[(b*Tc + t)*Dc + j] = val;
}

// ---------------- classic SGEMM: C = A[MxK] @ W[KxN] + bias, optional GELU ----
#define GBM 128
#define GBN 128
#define GBK 8
template<int EPI>
__global__ __launch_bounds__(256, 2)
void sgemm_kernel(const float* __restrict__ A, const float* __restrict__ W,
                  const float* __restrict__ bias, float* __restrict__ C,
                  int M, int N, int K)
{
    __shared__ float As[GBK][GBM];
    __shared__ float Bs[GBK][GBN];

    int tid = threadIdx.x;
    int bm = blockIdx.y, bn = blockIdx.x;

    int aRow = tid >> 1;            // 0..127
    int aCol = (tid & 1) << 2;      // 0 or 4
    int bRow = tid >> 5;            // 0..7
    int bCol = (tid & 31) << 2;     // 0..124

    const float* Aptr = A + (size_t)(bm*GBM + aRow)*K + aCol;
    const float* Wptr = W + (size_t)bRow*N + bn*GBN + bCol;

    int tx = tid & 15, ty = tid >> 4;
    float acc[8][8];
    #pragma unroll
    for (int i = 0; i < 8; i++)
        #pragma unroll
        for (int j = 0; j < 8; j++) acc[i][j] = 0.f;

    for (int k0 = 0; k0 < K; k0 += GBK) {
        float4 av = *(const float4*)Aptr;  Aptr += GBK;
        float4 bv = *(const float4*)Wptr;  Wptr += (size_t)GBK*N;
        As[aCol+0][aRow] = av.x; As[aCol+1][aRow] = av.y;
        As[aCol+2][aRow] = av.z; As[aCol+3][aRow] = av.w;
        *(float4*)&Bs[bRow][bCol] = bv;
        __syncthreads();

        #pragma unroll
        for (int kk = 0; kk < GBK; ++kk) {
            float ra[8], rb[8];
            *(float4*)&ra[0] = *(const float4*)&As[kk][ty*8];
            *(float4*)&ra[4] = *(const float4*)&As[kk][ty*8 + 4];
            *(float4*)&rb[0] = *(const float4*)&Bs[kk][tx*8];
            *(float4*)&rb[4] = *(const float4*)&Bs[kk][tx*8 + 4];
            #pragma unroll
            for (int i = 0; i < 8; i++)
                #pragma unroll
                for (int j = 0; j < 8; j++)
                    acc[i][j] += ra[i]*rb[j];
        }
        __syncthreads();
    }

    #pragma unroll
    for (int i = 0; i < 8; i++) {
        int row = bm*GBM + ty*8 + i;
        #pragma unroll
        for (int j4 = 0; j4 < 8; j4 += 4) {
            int col = bn*GBN + tx*8 + j4;
            float4 bb = *(const float4*)&bias[col];
            float4 o;
            o.x = acc[i][j4+0] + bb.x;
            o.y = acc[i][j4+1] + bb.y;
            o.z = acc[i][j4+2] + bb.z;
            o.w = acc[i][j4+3] + bb.w;
            if (EPI == 1) { // exact GELU
                o.x = 0.5f*o.x*(1.0f + erff(o.x*0.70710678118654752f));
                o.y = 0.5f*o.y*(1.0f + erff(o.y*0.70710678118654752f));
                o.z = 0.5f*o.z*(1.0f + erff(o.z*0.70710678118654752f));
                o.w = 0.5f*o.w*(1.0f + erff(o.w*0.70710678118654752f));
            }
            *(float4*)&C[(size_t)row*N + col] = o;
        }
    }
}

// ---------------- fused attention (scores + bias + causal + softmax + AV) ---
// grid (16, H, B), block 256. One block handles 32 q rows of one (b,h).
#define SS_PITCH 516
#define ATTN_SMEM ((64*33 + 64*68 + 32*SS_PITCH)*4 + 192*4)

__global__ __launch_bounds__(256)
void attn_kernel(const float* __restrict__ Q, const float* __restrict__ Kg,
                 const float* __restrict__ Vg,
                 const int* __restrict__ batters, const int* __restrict__ bowlers,
                 const float* __restrict__ rec_s, const float* __restrict__ bow_s,
                 const float* __restrict__ bat_s, int layer,
                 float* __restrict__ Og)
{
    extern __shared__ float sm[];
    float* Qst = sm;                    // [64][33]  Q transposed, padded
    float* KVs = Qst + 64*33;           // K transposed [64][68] / V natural [64][64]
    float* Sb  = KVs + 64*68;           // [32][516] score rows
    int*   ib  = (int*)(Sb + 32*SS_PITCH);
    int* bowQ = ib;       int* batQ = ib + 32;
    int* bowK = ib + 64;  int* batK = ib + 128;

    int qt = blockIdx.x, h = blockIdx.y, b = blockIdx.z;
    int tid = threadIdx.x;
    int q0 = qt*32;

    for (int idx = tid; idx < 32*64; idx += 256) {
        int q = idx >> 6, d = idx & 63;
        Qst[d*33 + q] = Q[(size_t)(b*Tc + q0 + q)*Dc + h*HDc + d];
    }
    if (tid < 32) {
        int qg = q0 + tid;
        bowQ[tid] = (qg < Sc) ? bowlers[b*Sc + qg] : -1;
        batQ[tid] = (qg < Sc) ? batters[b*Sc + qg] : -1;
    }
    __syncthreads();

    int ktmax = (q0 + 31)/64 + 1;
    int len   = ktmax*64;

    const float scl  = 0.125f; // 1/sqrt(64)
    const float recw = rec_s[layer];
    const float boww = bow_s[layer];
    const float batw = bat_s[layer];

    int tq = tid >> 4;      // 0..15 (pair of q rows)
    int tk = tid & 15;      // 0..15 (quad of k cols / d cols)
    int ql = tq*2;

    // ---- scores ----
    for (int kt = 0; kt < ktmax; ++kt) {
        int k0 = kt*64;
        for (int idx = tid; idx < 64*64; idx += 256) {
            int kk = idx >> 6, d = idx & 63;
            KVs[d*68 + kk] = Kg[(size_t)(b*Tc + k0 + kk)*Dc + h*HDc + d];
        }
        if (tid < 64) {
            int kg = k0 + tid;
            bowK[tid] = (kg < Sc) ? bowlers[b*Sc + kg] : -2;
            batK[tid] = (kg < Sc) ? batters[b*Sc + kg] : -2;
        }
        __syncthreads();

        float acc[2][4] = {{0,0,0,0},{0,0,0,0}};
        #pragma unroll 16
        for (int d = 0; d < 64; ++d) {
            float qv0 = Qst[d*33 + ql];
            float qv1 = Qst[d*33 + ql + 1];
            float4 kv = *(const float4*)&KVs[d*68 + tk*4];
            acc[0][0] += qv0*kv.x; acc[0][1] += qv0*kv.y;
            acc[0][2] += qv0*kv.z; acc[0][3] += qv0*kv.w;
            acc[1][0] += qv1*kv.x; acc[1][1] += qv1*kv.y;
            acc[1][2] += qv1*kv.z; acc[1][3] += qv1*kv.w;
        }
        #pragma unroll
        for (int i = 0; i < 2; ++i) {
            int qg = q0 + ql + i;
            int bq_ = bowQ[ql+i], aq_ = batQ[ql+i];
            #pragma unroll
            for (int j = 0; j < 4; ++j) {
                int kg = k0 + tk*4 + j;
                float s = acc[i][j]*scl;
                if (h == 0)      s += recw * (float)kg * (1.0f/512.0f);
                else if (h == 1) { if (qg == Sc || kg == Sc || bq_ == bowK[tk*4+j]) s += boww; }
                else if (h == 2) { if (qg == Sc || kg == Sc || aq_ == batK[tk*4+j]) s += batw; }
                if (kg > qg) s = -CUDART_INF_F;
                Sb[(ql+i)*SS_PITCH + kg] = s;
            }
        }
        __syncthreads();
    }

    // ---- softmax: warp w owns rows 4w..4w+3 ----
    int w = tid >> 5, lane = tid & 31;
    for (int r = w*4; r < w*4 + 4; ++r) {
        float m = -CUDART_INF_F;
        float vals[16];
        int cnt = 0;
        for (int c = lane; c < len; c += 32) {
            float vv = Sb[r*SS_PITCH + c];
            vals[cnt++] = vv;
            m = fmaxf(m, vv);
        }
        #pragma unroll
        for (int o = 16; o; o >>= 1) m = fmaxf(m, __shfl_xor_sync(0xffffffffu, m, o));
        float ssum = 0.f;
        for (int i = 0; i < cnt; ++i) { float e = expf(vals[i] - m); vals[i] = e; ssum += e; }
        #pragma unroll
        for (int o = 16; o; o >>= 1) ssum += __shfl_xor_sync(0xffffffffu, ssum, o);
        float inv = 1.0f/ssum;
        cnt = 0;
        for (int c = lane; c < len; c += 32) Sb[r*SS_PITCH + c] = vals[cnt++]*inv;
    }
    __syncthreads();

    // ---- AV ----
    float o2[2][4] = {{0,0,0,0},{0,0,0,0}};
    for (int kt = 0; kt < ktmax; ++kt) {
        int k0 = kt*64;
        for (int idx = tid; idx < 64*64; idx += 256) {
            int kk = idx >> 6, d = idx & 63;
            KVs[kk*64 + d] = Vg[(size_t)(b*Tc + k0 + kk)*Dc + h*HDc + d];
        }
        __syncthreads();
        #pragma unroll 16
        for (int kk = 0; kk < 64; ++kk) {
            float p0 = Sb[ql*SS_PITCH + k0 + kk];
            float p1 = Sb[(ql+1)*SS_PITCH + k0 + kk];
            float4 vv = *(const float4*)&KVs[kk*64 + tk*4];
            o2[0][0] += p0*vv.x; o2[0][1] += p0*vv.y; o2[0][2] += p0*vv.z; o2[0][3] += p0*vv.w;
            o2[1][0] += p1*vv.x; o2[1][1] += p1*vv.y; o2[1][2] += p1*vv.z; o2[1][3] += p1*vv.w;
        }
        __syncthreads();
    }
    #pragma unroll
    for (int i = 0; i < 2; ++i) {
        float4 ov; ov.x = o2[i][0]; ov.y = o2[i][1]; ov.z = o2[i][2]; ov.w = o2[i][3];
        *(float4*)&Og[(size_t)(b*Tc + q0 + ql + i)*Dc + h*HDc + tk*4] = ov;
    }
}

// ---------------- residual add + LayerNorm (in-place on x) ------------------
__global__ __launch_bounds__(512)
void add_ln_kernel(float* __restrict__ x, const float* __restrict__ r,
                   const float* __restrict__ g, const float* __restrict__ be)
{
    int tok = blockIdx.x;
    int j = threadIdx.x; // 512
    float v = x[(size_t)tok*Dc + j] + r[(size_t)tok*Dc + j];

    __shared__ float s1[16], s2[16];
    float a = v, b2 = v*v;
    #pragma unroll
    for (int o = 16; o; o >>= 1) {
        a  += __shfl_xor_sync(0xffffffffu, a, o);
        b2 += __shfl_xor_sync(0xffffffffu, b2, o);
    }
    int w = j >> 5, lane = j & 31;
    if (lane == 0) { s1[w] = a; s2[w] = b2; }
    __syncthreads();
    if (j < 16) {
        a = s1[j]; b2 = s2[j];
        #pragma unroll
        for (int o = 8; o; o >>= 1) {
            a  += __shfl_xor_sync(0x0000ffffu, a, o);
            b2 += __shfl_xor_sync(0x0000ffffu, b2, o);
        }
        if (j == 0) { s1[0] = a; s2[0] = b2; }
    }
    __syncthreads();
    float mu  = s1[0] * (1.0f/512.0f);
    float var = s2[0] * (1.0f/512.0f) - mu*mu;
    float y = (v - mu) * rsqrtf(var + 1e-5f) * g[j] + be[j];
    x[(size_t)tok*Dc + j] = y;
}

// ---------------- output head: out[b] = x[b, T-1] @ Wout + bout -------------
__global__ __launch_bounds__(512)
void out_kernel(const float* __restrict__ x, const float* __restrict__ Wout,
                const float* __restrict__ bout, float* __restrict__ out)
{
    int b = blockIdx.x;
    int n = threadIdx.x; // 512
    __shared__ float xs[512];
    xs[n] = x[(size_t)(b*Tc + Tc - 1)*Dc + n];
    __syncthreads();
    float acc = bout[n];
    #pragma unroll 8
    for (int d = 0; d < Dc; ++d)
        acc += xs[d] * Wout[(size_t)d*Dc + n];
    out[b*Dc + n] = acc;
}

// ---------------- launcher ---------------------------------------------------
extern "C" void kernel_launch(void* const* d_in, const int* in_sizes, int n_in,
                              void* d_out, int out_size)
{
    const float* runs    = (const float*)d_in[0];
    const float* wickets = (const float*)d_in[1];
    const float* overs   = (const float*)d_in[2];
    const int*   batters = (const int*)  d_in[3];
    const int*   bowlers = (const int*)  d_in[4];
    const float* pemb    = (const float*)d_in[5];
    const float* Wf      = (const float*)d_in[6];
    const float* bf      = (const float*)d_in[7];
    const float* qtok    = (const float*)d_in[8];
    const float* Wq      = (const float*)d_in[9];
    const float* bq      = (const float*)d_in[10];
    const float* Wk      = (const float*)d_in[11];
    const float* bk      = (const float*)d_in[12];
    const float* Wv      = (const float*)d_in[13];
    const float* bv      = (const float*)d_in[14];
    const float* Wo      = (const float*)d_in[15];
    const float* bo      = (const float*)d_in[16];
    const float* rec_s   = (const float*)d_in[17];
    const float* bow_s   = (const float*)d_in[18];
    const float* bat_s   = (const float*)d_in[19];
    const float* W1      = (const float*)d_in[20];
    const float* b1      = (const float*)d_in[21];
    const float* W2      = (const float*)d_in[22];
    const float* b2      = (const float*)d_in[23];
    const float* g1      = (const float*)d_in[24];
    const float* be1     = (const float*)d_in[25];
    const float* g2      = (const float*)d_in[26];
    const float* be2     = (const float*)d_in[27];
    const float* Wout    = (const float*)d_in[28];
    const float* bout    = (const float*)d_in[29];
    float* out = (float*)d_out;

    float *x_, *q_, *k_, *v_, *att_, *tmp_, *ff_;
    cudaGetSymbolAddress((void**)&x_,   g_x);
    cudaGetSymbolAddress((void**)&q_,   g_q);
    cudaGetSymbolAddress((void**)&k_,   g_k);
    cudaGetSymbolAddress((void**)&v_,   g_v);
    cudaGetSymbolAddress((void**)&att_, g_att);
    cudaGetSymbolAddress((void**)&tmp_, g_tmp);
    cudaGetSymbolAddress((void**)&ff_,  g_ff);

    cudaFuncSetAttribute(attn_kernel,
                         cudaFuncAttributeMaxDynamicSharedMemorySize, ATTN_SMEM);

    embed_kernel<<<Bc*Tc, 512>>>(runs, wickets, overs, batters, bowlers,
                                 pemb, Wf, bf, qtok, x_);

    dim3 g512(Dc/GBN, Mc/GBM);     // (4, 128)
    dim3 g2048(DFFc/GBN, Mc/GBM);  // (16, 128)
    dim3 gattn(16, Hc, Bc);

    for (int l = 0; l < Lc; ++l) {
        const float* Wql = Wq + (size_t)l*Dc*Dc;
        const float* Wkl = Wk + (size_t)l*Dc*Dc;
        const float* Wvl = Wv + (size_t)l*Dc*Dc;
        const float* Wol = Wo + (size_t)l*Dc*Dc;

        sgemm_kernel<0><<<g512, 256>>>(x_, Wql, bq + l*Dc, q_, Mc, Dc, Dc);
        sgemm_kernel<0><<<g512, 256>>>(x_, Wkl, bk + l*Dc, k_, Mc, Dc, Dc);
        sgemm_kernel<0><<<g512, 256>>>(x_, Wvl, bv + l*Dc, v_, Mc, Dc, Dc);

        attn_kernel<<<gattn, 256, ATTN_SMEM>>>(q_, k_, v_, batters, bowlers,
                                               rec_s, bow_s, bat_s, l, att_);

        sgemm_kernel<0><<<g512, 256>>>(att_, Wol, bo + l*Dc, tmp_, Mc, Dc, Dc);
        add_ln_kernel<<<Mc, 512>>>(x_, tmp_, g1 + l*Dc, be1 + l*Dc);

        sgemm_kernel<1><<<g2048, 256>>>(x_, W1 + (size_t)l*Dc*DFFc, b1 + l*DFFc,
                                        ff_, Mc, DFFc, Dc);
        sgemm_kernel<0><<<g512, 256>>>(ff_, W2 + (size_t)l*DFFc*Dc, b2 + l*Dc,
                                       tmp_, Mc, Dc, DFFc);
        add_ln_kernel<<<Mc, 512>>>(x_, tmp_, g2 + l*Dc, be2 + l*Dc);
    }

    out_kernel<<<Bc, 512>>>(x_, Wout, bout, out);
}

// round 2
// speedup vs baseline: 2.3853x; 2.3853x over previous
#include <cuda_runtime.h>
#include <cuda_bf16.h>
#include <math_constants.h>
#include <cstdint>

// Problem constants
#define Bc   32
#define Sc   511
#define Tc   512
#define Dc   512
#define Hc   8
#define HDc  64
#define Lc   4
#define PDc  32
#define FDc  448     // D - 2*PD
#define DFFc 2048
#define Mc   (Bc*Tc) // 16384 tokens

// ---------------- scratch (device globals; no allocation allowed) ----------
__device__ float g_x  [Mc*Dc];
__device__ float g_q  [Mc*Dc];
__device__ float g_k  [Mc*Dc];
__device__ float g_v  [Mc*Dc];
__device__ float g_att[Mc*Dc];
__device__ float g_tmp[Mc*Dc];
__device__ float g_ff [Mc*DFFc];

// ---------------- embedding + positional encoding ---------------------------
__global__ void embed_kernel(const float* __restrict__ runs,
                             const float* __restrict__ wickets,
                             const float* __restrict__ overs,
                             const int*   __restrict__ batters,
                             const int*   __restrict__ bowlers,
                             const float* __restrict__ pemb,
                             const float* __restrict__ Wf,
                             const float* __restrict__ bf,
                             const float* __restrict__ qtok,
                             float* __restrict__ x)
{
    int bt = blockIdx.x;
    int b  = bt / Tc;
    int t  = bt % Tc;
    int j  = threadIdx.x; // 0..511

    float val;
    if (t < Sc) {
        if (j < FDc) {
            float r = runs   [b*Sc + t];
            float w = wickets[b*Sc + t];
            float o = overs  [b*Sc + t];
            val = r*Wf[j] + w*Wf[FDc + j] + o*Wf[2*FDc + j] + bf[j];
        } else if (j < FDc + PDc) {
            val = pemb[batters[b*Sc + t]*PDc + (j - FDc)];
        } else {
            val = pemb[bowlers[b*Sc + t]*PDc + (j - FDc - PDc)];
        }
    } else {
        val = qtok[j];
    }
    int   i2  = j & ~1;
    float dv  = expf((float)i2 * -0.0179889460390111f); // ln(10000)/512
    float ang = (float)t * dv;
    val += (j & 1) ? cosf(ang) : sinf(ang);
    x[(b*Tc + t)*Dc + j] = val;
}

// ---------------- tf32 tensor-core GEMM -------------------------------------
// C[M,N] = A[M,K] @ W[K,N] + bias, optional exact GELU.
// Block tile 128x128x32, 256 threads, 8 warps (2x4), warp tile 64x32.
// mma.sync.aligned.m16n8k8.row.col.f32.tf32.tf32.f32
#define TBM 128
#define TBN 128
#define TBK 32
#define AST 36    // As row stride (words): gid*4+tig bijective mod 32 -> conflict-free
#define BST 136   // Bs row stride (words): tig*8+gid bijective mod 32 -> conflict-free

__device__ __forceinline__ uint32_t smem_u32(const void* p) {
    return (uint32_t)__cvta_generic_to_shared(p);
}

__device__ __forceinline__ void tg_load_stage(
    const float* __restrict__ A, const float* __restrict__ W,
    float* __restrict__ As, float* __restrict__ Bs,
    int bm, int bn, int k0, int K, int N, int tid)
{
    // A tile: 128 rows x 32 cols -> 1024 16B chunks, 4 per thread
    int ar = tid >> 3, aq = tid & 7;
    const float* ap = A + (size_t)(bm*TBM + ar)*K + k0 + aq*4;
    uint32_t ad = smem_u32(As + ar*AST + aq*4);
    #pragma unroll
    for (int i = 0; i < 4; i++) {
        asm volatile("cp.async.cg.shared.global [%0], [%1], 16;\n"
                     :: "r"(ad + i*32*AST*4), "l"(ap + (size_t)i*32*K));
    }
    // B tile: 32 rows x 128 cols -> 1024 16B chunks, 4 per thread
    int br = tid >> 5, bq = tid & 31;
    const float* bp = W + (size_t)(k0 + br)*N + bn*TBN + bq*4;
    uint32_t bd = smem_u32(Bs + br*BST + bq*4);
    #pragma unroll
    for (int i = 0; i < 4; i++) {
        asm volatile("cp.async.cg.shared.global [%0], [%1], 16;\n"
                     :: "r"(bd + i*8*BST*4), "l"(bp + (size_t)i*8*N));
    }
    asm volatile("cp.async.commit_group;\n");
}

template<int EPI>
__global__ __launch_bounds__(256, 2)
void tgemm_kernel(const float* __restrict__ A, const float* __restrict__ W,
                  const float* __restrict__ bias, float* __restrict__ C,
                  int M, int N, int K)
{
    extern __shared__ float sm[];
    float* As = sm;                       // [2][128*AST]
    float* Bs = sm + 2*TBM*AST;           // [2][32*BST]

    int tid = threadIdx.x;
    int bm = blockIdx.y, bn = blockIdx.x;
    int w = tid >> 5, lane = tid & 31;
    int gid = lane >> 2, tig = lane & 3;
    int wm = w >> 2, wn = w & 3;          // wm 0..1, wn 0..3

    float acc[4][4][4];
    #pragma unroll
    for (int i = 0; i < 4; i++)
        #pragma unroll
        for (int j = 0; j < 4; j++)
            #pragma unroll
            for (int r = 0; r < 4; r++) acc[i][j][r] = 0.f;

    int nkt = K / TBK;
    tg_load_stage(A, W, As, Bs, bm, bn, 0, K, N, tid);

    for (int kt = 0; kt < nkt; ++kt) {
        int cur = kt & 1;
        if (kt + 1 < nkt) {
            tg_load_stage(A, W, As + (cur^1)*TBM*AST, Bs + (cur^1)*32*BST,
                          bm, bn, (kt+1)*TBK, K, N, tid);
            asm volatile("cp.async.wait_group 1;\n");
        } else {
            asm volatile("cp.async.wait_group 0;\n");
        }
        __syncthreads();

        const float* Asc = As + cur*TBM*AST;
        const float* Bsc = Bs + cur*32*BST;

        #pragma unroll
        for (int kc = 0; kc < 4; ++kc) {
            uint32_t a[4][4], b[4][2];
            #pragma unroll
            for (int i = 0; i < 4; i++) {
                int r0 = wm*64 + 16*i + gid;
                a[i][0] = __float_as_uint(Asc[(r0    )*AST + kc*8 + tig    ]);
                a[i][1] = __float_as_uint(Asc[(r0 + 8)*AST + kc*8 + tig    ]);
                a[i][2] = __float_as_uint(Asc[(r0    )*AST + kc*8 + tig + 4]);
                a[i][3] = __float_as_uint(Asc[(r0 + 8)*AST + kc*8 + tig + 4]);
            }
            #pragma unroll
            for (int j = 0; j < 4; j++) {
                int c0 = wn*32 + 8*j + gid;
                b[j][0] = __float_as_uint(Bsc[(kc*8 + tig    )*BST + c0]);
                b[j][1] = __float_as_uint(Bsc[(kc*8 + tig + 4)*BST + c0]);
            }
            #pragma unroll
            for (int i = 0; i < 4; i++)
                #pragma unroll
                for (int j = 0; j < 4; j++) {
                    asm volatile(
                        "mma.sync.aligned.m16n8k8.row.col.f32.tf32.tf32.f32 "
                        "{%0,%1,%2,%3}, {%4,%5,%6,%7}, {%8,%9}, {%0,%1,%2,%3};\n"
                        : "+f"(acc[i][j][0]), "+f"(acc[i][j][1]),
                          "+f"(acc[i][j][2]), "+f"(acc[i][j][3])
                        : "r"(a[i][0]), "r"(a[i][1]), "r"(a[i][2]), "r"(a[i][3]),
                          "r"(b[j][0]), "r"(b[j][1]));
                }
        }
        __syncthreads();
    }

    // epilogue
    #pragma unroll
    for (int i = 0; i < 4; i++) {
        int r = bm*TBM + wm*64 + 16*i + gid;
        #pragma unroll
        for (int j = 0; j < 4; j++) {
            int c = bn*TBN + wn*32 + 8*j + 2*tig;
            float bx = bias[c], by = bias[c+1];
            float v0 = acc[i][j][0] + bx;
            float v1 = acc[i][j][1] + by;
            float v2 = acc[i][j][2] + bx;
            float v3 = acc[i][j][3] + by;
            if (EPI == 1) {
                v0 = 0.5f*v0*(1.0f + erff(v0*0.70710678118654752f));
                v1 = 0.5f*v1*(1.0f + erff(v1*0.70710678118654752f));
                v2 = 0.5f*v2*(1.0f + erff(v2*0.70710678118654752f));
                v3 = 0.5f*v3*(1.0f + erff(v3*0.70710678118654752f));
            }
            float2 p0; p0.x = v0; p0.y = v1;
            float2 p1; p1.x = v2; p1.y = v3;
            *(float2*)&C[(size_t)r*N + c]       = p0;
            *(float2*)&C[(size_t)(r+8)*N + c]   = p1;
        }
    }
}
#define TGEMM_SMEM ((2*TBM*AST + 2*32*BST)*4)

// ---------------- fused attention (scores + bias + causal + softmax + AV) ---
#define SS_PITCH 516
#define ATTN_SMEM ((64*33 + 64*68 + 32*SS_PITCH)*4 + 192*4)

__global__ __launch_bounds__(256)
void attn_kernel(const float* __restrict__ Q, const float* __restrict__ Kg,
                 const float* __restrict__ Vg,
                 const int* __restrict__ batters, const int* __restrict__ bowlers,
                 const float* __restrict__ rec_s, const float* __restrict__ bow_s,
                 const float* __restrict__ bat_s, int layer,
                 float* __restrict__ Og)
{
    extern __shared__ float sm[];
    float* Qst = sm;                    // [64][33]  Q transposed, padded
    float* KVs = Qst + 64*33;           // K transposed [64][68] / V natural [64][64]
    float* Sb  = KVs + 64*68;           // [32][516] score rows
    int*   ib  = (int*)(Sb + 32*SS_PITCH);
    int* bowQ = ib;       int* batQ = ib + 32;
    int* bowK = ib + 64;  int* batK = ib + 128;

    int qt = blockIdx.x, h = blockIdx.y, b = blockIdx.z;
    int tid = threadIdx.x;
    int q0 = qt*32;

    for (int idx = tid; idx < 32*64; idx += 256) {
        int q = idx >> 6, d = idx & 63;
        Qst[d*33 + q] = Q[(size_t)(b*Tc + q0 + q)*Dc + h*HDc + d];
    }
    if (tid < 32) {
        int qg = q0 + tid;
        bowQ[tid] = (qg < Sc) ? bowlers[b*Sc + qg] : -1;
        batQ[tid] = (qg < Sc) ? batters[b*Sc + qg] : -1;
    }
    __syncthreads();

    int ktmax = (q0 + 31)/64 + 1;
    int len   = ktmax*64;

    const float scl  = 0.125f;
    const float recw = rec_s[layer];
    const float boww = bow_s[layer];
    const float batw = bat_s[layer];

    int tq = tid >> 4;
    int tk = tid & 15;
    int ql = tq*2;

    for (int kt = 0; kt < ktmax; ++kt) {
        int k0 = kt*64;
        for (int idx = tid; idx < 64*64; idx += 256) {
            int kk = idx >> 6, d = idx & 63;
            KVs[d*68 + kk] = Kg[(size_t)(b*Tc + k0 + kk)*Dc + h*HDc + d];
        }
        if (tid < 64) {
            int kg = k0 + tid;
            bowK[tid] = (kg < Sc) ? bowlers[b*Sc + kg] : -2;
            batK[tid] = (kg < Sc) ? batters[b*Sc + kg] : -2;
        }
        __syncthreads();

        float acc[2][4] = {{0,0,0,0},{0,0,0,0}};
        #pragma unroll 16
        for (int d = 0; d < 64; ++d) {
            float qv0 = Qst[d*33 + ql];
            float qv1 = Qst[d*33 + ql + 1];
            float4 kv = *(const float4*)&KVs[d*68 + tk*4];
            acc[0][0] += qv0*kv.x; acc[0][1] += qv0*kv.y;
            acc[0][2] += qv0*kv.z; acc[0][3] += qv0*kv.w;
            acc[1][0] += qv1*kv.x; acc[1][1] += qv1*kv.y;
            acc[1][2] += qv1*kv.z; acc[1][3] += qv1*kv.w;
        }
        #pragma unroll
        for (int i = 0; i < 2; ++i) {
            int qg = q0 + ql + i;
            int bq_ = bowQ[ql+i], aq_ = batQ[ql+i];
            #pragma unroll
            for (int j = 0; j < 4; ++j) {
                int kg = k0 + tk*4 + j;
                float s = acc[i][j]*scl;
                if (h == 0)      s += recw * (float)kg * (1.0f/512.0f);
                else if (h == 1) { if (qg == Sc || kg == Sc || bq_ == bowK[tk*4+j]) s += boww; }
                else if (h == 2) { if (qg == Sc || kg == Sc || aq_ == batK[tk*4+j]) s += batw; }
                if (kg > qg) s = -CUDART_INF_F;
                Sb[(ql+i)*SS_PITCH + kg] = s;
            }
        }
        __syncthreads();
    }

    int w = tid >> 5, lane = tid & 31;
    for (int r = w*4; r < w*4 + 4; ++r) {
        float m = -CUDART_INF_F;
        float vals[16];
        int cnt = 0;
        for (int c = lane; c < len; c += 32) {
            float vv = Sb[r*SS_PITCH + c];
            vals[cnt++] = vv;
            m = fmaxf(m, vv);
        }
        #pragma unroll
        for (int o = 16; o; o >>= 1) m = fmaxf(m, __shfl_xor_sync(0xffffffffu, m, o));
        float ssum = 0.f;
        for (int i = 0; i < cnt; ++i) { float e = expf(vals[i] - m); vals[i] = e; ssum += e; }
        #pragma unroll
        for (int o = 16; o; o >>= 1) ssum += __shfl_xor_sync(0xffffffffu, ssum, o);
        float inv = 1.0f/ssum;
        cnt = 0;
        for (int c = lane; c < len; c += 32) Sb[r*SS_PITCH + c] = vals[cnt++]*inv;
    }
    __syncthreads();

    float o2[2][4] = {{0,0,0,0},{0,0,0,0}};
    for (int kt = 0; kt < ktmax; ++kt) {
        int k0 = kt*64;
        for (int idx = tid; idx < 64*64; idx += 256) {
            int kk = idx >> 6, d = idx & 63;
            KVs[kk*64 + d] = Vg[(size_t)(b*Tc + k0 + kk)*Dc + h*HDc + d];
        }
        __syncthreads();
        #pragma unroll 16
        for (int kk = 0; kk < 64; ++kk) {
            float p0 = Sb[ql*SS_PITCH + k0 + kk];
            float p1 = Sb[(ql+1)*SS_PITCH + k0 + kk];
            float4 vv = *(const float4*)&KVs[kk*64 + tk*4];
            o2[0][0] += p0*vv.x; o2[0][1] += p0*vv.y; o2[0][2] += p0*vv.z; o2[0][3] += p0*vv.w;
            o2[1][0] += p1*vv.x; o2[1][1] += p1*vv.y; o2[1][2] += p1*vv.z; o2[1][3] += p1*vv.w;
        }
        __syncthreads();
    }
    #pragma unroll
    for (int i = 0; i < 2; ++i) {
        float4 ov; ov.x = o2[i][0]; ov.y = o2[i][1]; ov.z = o2[i][2]; ov.w = o2[i][3];
        *(float4*)&Og[(size_t)(b*Tc + q0 + ql + i)*Dc + h*HDc + tk*4] = ov;
    }
}

// ---------------- residual add + LayerNorm (in-place on x) ------------------
__global__ __launch_bounds__(512)
void add_ln_kernel(float* __restrict__ x, const float* __restrict__ r,
                   const float* __restrict__ g, const float* __restrict__ be)
{
    int tok = blockIdx.x;
    int j = threadIdx.x;
    float v = x[(size_t)tok*Dc + j] + r[(size_t)tok*Dc + j];

    __shared__ float s1[16], s2[16];
    float a = v, b2 = v*v;
    #pragma unroll
    for (int o = 16; o; o >>= 1) {
        a  += __shfl_xor_sync(0xffffffffu, a, o);
        b2 += __shfl_xor_sync(0xffffffffu, b2, o);
    }
    int w = j >> 5, lane = j & 31;
    if (lane == 0) { s1[w] = a; s2[w] = b2; }
    __syncthreads();
    if (j < 16) {
        a = s1[j]; b2 = s2[j];
        #pragma unroll
        for (int o = 8; o; o >>= 1) {
            a  += __shfl_xor_sync(0x0000ffffu, a, o);
            b2 += __shfl_xor_sync(0x0000ffffu, b2, o);
        }
        if (j == 0) { s1[0] = a; s2[0] = b2; }
    }
    __syncthreads();
    float mu  = s1[0] * (1.0f/512.0f);
    float var = s2[0] * (1.0f/512.0f) - mu*mu;
    float y = (v - mu) * rsqrtf(var + 1e-5f) * g[j] + be[j];
    x[(size_t)tok*Dc + j] = y;
}

// ---------------- output head: out[b] = x[b, T-1] @ Wout + bout -------------
__global__ __launch_bounds__(512)
void out_kernel(const float* __restrict__ x, const float* __restrict__ Wout,
                const float* __restrict__ bout, float* __restrict__ out)
{
    int b = blockIdx.x;
    int n = threadIdx.x;
    __shared__ float xs[512];
    xs[n] = x[(size_t)(b*Tc + Tc - 1)*Dc + n];
    __syncthreads();
    float acc = bout[n];
    #pragma unroll 8
    for (int d = 0; d < Dc; ++d)
        acc += xs[d] * Wout[(size_t)d*Dc + n];
    out[b*Dc + n] = acc;
}

// ---------------- launcher ---------------------------------------------------
extern "C" void kernel_launch(void* const* d_in, const int* in_sizes, int n_in,
                              void* d_out, int out_size)
{
    const float* runs    = (const float*)d_in[0];
    const float* wickets = (const float*)d_in[1];
    const float* overs   = (const float*)d_in[2];
    const int*   batters = (const int*)  d_in[3];
    const int*   bowlers = (const int*)  d_in[4];
    const float* pemb    = (const float*)d_in[5];
    const float* Wf      = (const float*)d_in[6];
    const float* bf      = (const float*)d_in[7];
    const float* qtok    = (const float*)d_in[8];
    const float* Wq      = (const float*)d_in[9];
    const float* bq      = (const float*)d_in[10];
    const float* Wk      = (const float*)d_in[11];
    const float* bk      = (const float*)d_in[12];
    const float* Wv      = (const float*)d_in[13];
    const float* bv      = (const float*)d_in[14];
    const float* Wo      = (const float*)d_in[15];
    const float* bo      = (const float*)d_in[16];
    const float* rec_s   = (const float*)d_in[17];
    const float* bow_s   = (const float*)d_in[18];
    const float* bat_s   = (const float*)d_in[19];
    const float* W1      = (const float*)d_in[20];
    const float* b1      = (const float*)d_in[21];
    const float* W2      = (const float*)d_in[22];
    const float* b2      = (const float*)d_in[23];
    const float* g1      = (const float*)d_in[24];
    const float* be1     = (const float*)d_in[25];
    const float* g2      = (const float*)d_in[26];
    const float* be2     = (const float*)d_in[27];
    const float* Wout    = (const float*)d_in[28];
    const float* bout    = (const float*)d_in[29];
    float* out = (float*)d_out;

    float *x_, *q_, *k_, *v_, *att_, *tmp_, *ff_;
    cudaGetSymbolAddress((void**)&x_,   g_x);
    cudaGetSymbolAddress((void**)&q_,   g_q);
    cudaGetSymbolAddress((void**)&k_,   g_k);
    cudaGetSymbolAddress((void**)&v_,   g_v);
    cudaGetSymbolAddress((void**)&att_, g_att);
    cudaGetSymbolAddress((void**)&tmp_, g_tmp);
    cudaGetSymbolAddress((void**)&ff_,  g_ff);

    cudaFuncSetAttribute(attn_kernel,
                         cudaFuncAttributeMaxDynamicSharedMemorySize, ATTN_SMEM);
    cudaFuncSetAttribute(tgemm_kernel<0>,
                         cudaFuncAttributeMaxDynamicSharedMemorySize, TGEMM_SMEM);
    cudaFuncSetAttribute(tgemm_kernel<1>,
                         cudaFuncAttributeMaxDynamicSharedMemorySize, TGEMM_SMEM);

    embed_kernel<<<Bc*Tc, 512>>>(runs, wickets, overs, batters, bowlers,
                                 pemb, Wf, bf, qtok, x_);

    dim3 g512(Dc/TBN, Mc/TBM);     // (4, 128)
    dim3 g2048(DFFc/TBN, Mc/TBM);  // (16, 128)
    dim3 gattn(16, Hc, Bc);

    for (int l = 0; l < Lc; ++l) {
        const float* Wql = Wq + (size_t)l*Dc*Dc;
        const float* Wkl = Wk + (size_t)l*Dc*Dc;
        const float* Wvl = Wv + (size_t)l*Dc*Dc;
        const float* Wol = Wo + (size_t)l*Dc*Dc;

        tgemm_kernel<0><<<g512, 256, TGEMM_SMEM>>>(x_, Wql, bq + l*Dc, q_, Mc, Dc, Dc);
        tgemm_kernel<0><<<g512, 256, TGEMM_SMEM>>>(x_, Wkl, bk + l*Dc, k_, Mc, Dc, Dc);
        tgemm_kernel<0><<<g512, 256, TGEMM_SMEM>>>(x_, Wvl, bv + l*Dc, v_, Mc, Dc, Dc);

        attn_kernel<<<gattn, 256, ATTN_SMEM>>>(q_, k_, v_, batters, bowlers,
                                               rec_s, bow_s, bat_s, l, att_);

        tgemm_kernel<0><<<g512, 256, TGEMM_SMEM>>>(att_, Wol, bo + l*Dc, tmp_, Mc, Dc, Dc);
        add_ln_kernel<<<Mc, 512>>>(x_, tmp_, g1 + l*Dc, be1 + l*Dc);

        tgemm_kernel<1><<<g2048, 256, TGEMM_SMEM>>>(x_, W1 + (size_t)l*Dc*DFFc, b1 + l*DFFc,
                                                    ff_, Mc, DFFc, Dc);
        tgemm_kernel<0><<<g512, 256, TGEMM_SMEM>>>(ff_, W2 + (size_t)l*DFFc*Dc, b2 + l*Dc,
                                                   tmp_, Mc, Dc, DFFc);
        add_ln_kernel<<<Mc, 512>>>(x_, tmp_, g2 + l*Dc, be2 + l*Dc);
    }

    out_kernel<<<Bc, 512>>>(x_, Wout, bout, out);
}